// round 1
// baseline (speedup 1.0000x reference)
#include <cuda_runtime.h>
#include <math.h>

#define NMAX 100000
#define EMAX 1600000
#define DIN  256
#define DOUT 128

// ---- scratch (device globals; no allocations allowed) ----
__device__ float g_h[NMAX * DOUT];     // h = X*W + b            (51.2 MB, L2-resident)
__device__ float g_a2[NMAX];           // s[n] = sum_c |h|*a2_w  (row-softmax key)
__device__ int   g_cnt[NMAX];          // edge histogram by row
__device__ int   g_off[NMAX + 1];      // CSR offsets
__device__ int   g_cur[NMAX];          // scatter cursors
__device__ int   g_col[EMAX];          // CSR cols
__device__ float g_val[EMAX];          // CSR signed values
__device__ int   g_bsum[128];          // scan block sums

// ---------------------------------------------------------------------------
__global__ void k_zero(int N) {
    int i = blockIdx.x * blockDim.x + threadIdx.x;
    if (i < N) g_cnt[i] = 0;
}

// ---------------------------------------------------------------------------
// GEMM: h = feat @ W + b, fused a2 row-reduction s = sum_c |h|*a2_w
// BM=64 rows, BN=128 cols (full), BK=32. 256 threads, per-thread 8x4 outputs.
__global__ __launch_bounds__(256) void k_gemm(const float* __restrict__ feat,
                                              const float* __restrict__ W,
                                              const float* __restrict__ bias,
                                              const float* __restrict__ a2w,
                                              int N) {
    __shared__ float As[64][32];
    __shared__ float Bs[32][128];

    const int t   = threadIdx.x;
    const int tx  = t & 31;          // col group (lane)
    const int ty  = t >> 5;          // row group (warp)
    const int row0 = blockIdx.x * 64;

    float acc[8][4];
#pragma unroll
    for (int i = 0; i < 8; i++)
#pragma unroll
        for (int j = 0; j < 4; j++) acc[i][j] = 0.f;

    const float4* feat4 = (const float4*)feat;
    const float4* W4    = (const float4*)W;

    for (int k0 = 0; k0 < DIN; k0 += 32) {
        // load A tile: 64x32 floats = 512 float4, 2 per thread
#pragma unroll
        for (int li = 0; li < 2; li++) {
            int e  = t + li * 256;
            int r  = e >> 3;          // 8 float4 per row
            int k4 = e & 7;
            int gr = row0 + r;
            float4 v = make_float4(0.f, 0.f, 0.f, 0.f);
            if (gr < N) v = feat4[gr * (DIN / 4) + (k0 >> 2) + k4];
            *(float4*)&As[r][k4 * 4] = v;
        }
        // load B tile: 32x128 floats = 1024 float4, 4 per thread
#pragma unroll
        for (int li = 0; li < 4; li++) {
            int e  = t + li * 256;
            int kr = e >> 5;          // 32 float4 per row
            int c4 = e & 31;
            *(float4*)&Bs[kr][c4 * 4] = W4[(k0 + kr) * (DOUT / 4) + c4];
        }
        __syncthreads();

#pragma unroll
        for (int kk = 0; kk < 32; kk++) {
            float4 bv = *(const float4*)&Bs[kk][tx * 4];
#pragma unroll
            for (int i = 0; i < 8; i++) {
                float a = As[ty * 8 + i][kk];
                acc[i][0] += a * bv.x;
                acc[i][1] += a * bv.y;
                acc[i][2] += a * bv.z;
                acc[i][3] += a * bv.w;
            }
        }
        __syncthreads();
    }

    // epilogue: add bias, store h, fused |h|.a2_w warp reduction per row
    float4 b4  = *(const float4*)&bias[tx * 4];
    float4 aw4 = *(const float4*)&a2w[tx * 4];
#pragma unroll
    for (int i = 0; i < 8; i++) {
        int gr = row0 + ty * 8 + i;
        if (gr >= N) break;
        float4 h;
        h.x = acc[i][0] + b4.x;
        h.y = acc[i][1] + b4.y;
        h.z = acc[i][2] + b4.z;
        h.w = acc[i][3] + b4.w;
        *(float4*)&g_h[gr * DOUT + tx * 4] = h;
        float s = fabsf(h.x) * aw4.x + fabsf(h.y) * aw4.y +
                  fabsf(h.z) * aw4.z + fabsf(h.w) * aw4.w;
#pragma unroll
        for (int o = 16; o > 0; o >>= 1) s += __shfl_xor_sync(0xffffffffu, s, o);
        if (tx == 0) g_a2[gr] = s;
    }
}

// ---------------------------------------------------------------------------
__global__ void k_hist(const int* __restrict__ row, int E) {
    int e = blockIdx.x * blockDim.x + threadIdx.x;
    if (e < E) atomicAdd(&g_cnt[row[e]], 1);
}

// per-1024 block scan; local-exclusive into g_off, block totals into g_bsum
__global__ __launch_bounds__(1024) void k_scan1(int N) {
    int i    = blockIdx.x * 1024 + threadIdx.x;
    int lane = threadIdx.x & 31;
    int wid  = threadIdx.x >> 5;
    int v = (i < N) ? g_cnt[i] : 0;
    int x = v;
#pragma unroll
    for (int o = 1; o < 32; o <<= 1) {
        int y = __shfl_up_sync(0xffffffffu, x, o);
        if (lane >= o) x += y;
    }
    __shared__ int wsum[32];
    if (lane == 31) wsum[wid] = x;
    __syncthreads();
    if (wid == 0) {
        int w = wsum[lane];
#pragma unroll
        for (int o = 1; o < 32; o <<= 1) {
            int y = __shfl_up_sync(0xffffffffu, w, o);
            if (lane >= o) w += y;
        }
        wsum[lane] = w;
    }
    __syncthreads();
    int incl = x + (wid > 0 ? wsum[wid - 1] : 0);
    if (i < N) g_off[i] = incl - v;
    if (threadIdx.x == 1023) g_bsum[blockIdx.x] = incl;
}

// exclusive scan of block sums (nb <= 128)
__global__ __launch_bounds__(128) void k_scan2(int nb) {
    __shared__ int s[128];
    int t = threadIdx.x;
    int v = (t < nb) ? g_bsum[t] : 0;
    s[t] = v;
    __syncthreads();
#pragma unroll
    for (int o = 1; o < 128; o <<= 1) {
        int y = (t >= o) ? s[t - o] : 0;
        __syncthreads();
        s[t] += y;
        __syncthreads();
    }
    if (t < nb) g_bsum[t] = s[t] - v;
}

__global__ void k_scan3(int N, int E) {
    int i = blockIdx.x * blockDim.x + threadIdx.x;
    if (i < N) {
        int val = g_off[i] + g_bsum[i >> 10];
        g_off[i] = val;
        g_cur[i] = val;
    }
    if (i == 0) g_off[N] = E;
}

__global__ void k_scatter(const int* __restrict__ row, const int* __restrict__ col,
                          const float* __restrict__ values, int E) {
    int e = blockIdx.x * blockDim.x + threadIdx.x;
    if (e < E) {
        int p = atomicAdd(&g_cur[row[e]], 1);
        g_col[p] = col[e];
        g_val[p] = values[e];
    }
}

// ---------------------------------------------------------------------------
// One warp per row: softmax over edges (max, denom), then attention-weighted
// SpMM gather h[col] (float4 per lane covers the 128 cols), scaled output.
__global__ __launch_bounds__(256) void k_spmm(float4* __restrict__ out4, int N) {
    int gw   = (blockIdx.x * blockDim.x + threadIdx.x) >> 5;
    int lane = threadIdx.x & 31;
    if (gw >= N) return;

    int base = g_off[gw];
    int end  = g_off[gw + 1];
    int deg  = end - base;

    if (deg == 0) {
        out4[gw * 32 + lane] = make_float4(0.f, 0.f, 0.f, 0.f);
        return;
    }

    float m = -1e30f;
    for (int j = base + lane; j < end; j += 32)
        m = fmaxf(m, g_a2[g_col[j]]);
#pragma unroll
    for (int o = 16; o > 0; o >>= 1)
        m = fmaxf(m, __shfl_xor_sync(0xffffffffu, m, o));

    float d = 0.f;
    for (int j = base + lane; j < end; j += 32)
        d += __expf(g_a2[g_col[j]] - m);
#pragma unroll
    for (int o = 16; o > 0; o >>= 1)
        d += __shfl_xor_sync(0xffffffffu, d, o);

    const float4* h4 = (const float4*)g_h;
    float4 acc = make_float4(0.f, 0.f, 0.f, 0.f);
    for (int j = base; j < end; ++j) {
        int   c = g_col[j];                       // broadcast load
        float w = __expf(g_a2[c] - m) * g_val[j]; // broadcast loads
        float4 hv = h4[c * 32 + lane];            // 512B/warp gather (L2 hit)
        acc.x += w * hv.x;
        acc.y += w * hv.y;
        acc.z += w * hv.z;
        acc.w += w * hv.w;
    }
    float inv = 1.f / d;
    acc.x *= inv; acc.y *= inv; acc.z *= inv; acc.w *= inv;
    out4[gw * 32 + lane] = acc;
}

// ---------------------------------------------------------------------------
extern "C" void kernel_launch(void* const* d_in, const int* in_sizes, int n_in,
                              void* d_out, int out_size) {
    const float* feat   = (const float*)d_in[0];
    const float* values = (const float*)d_in[1];
    const float* W      = (const float*)d_in[2];
    const float* bias   = (const float*)d_in[3];
    // d_in[4] (a1_w), d_in[5] (a1_b), d_in[7] (a2_b) cancel in the row softmax
    const float* a2w    = (const float*)d_in[6];
    const int*   row    = (const int*)d_in[8];
    const int*   col    = (const int*)d_in[9];

    const int N = in_sizes[0] / DIN;
    const int E = in_sizes[1];

    k_zero<<<(N + 255) / 256, 256>>>(N);
    k_gemm<<<(N + 63) / 64, 256>>>(feat, W, bias, a2w, N);
    k_hist<<<(E + 255) / 256, 256>>>(row, E);

    int nb = (N + 1023) / 1024;
    k_scan1<<<nb, 1024>>>(N);
    k_scan2<<<1, 128>>>(nb);
    k_scan3<<<(N + 255) / 256, 256>>>(N, E);
    k_scatter<<<(E + 255) / 256, 256>>>(row, col, values, E);

    long long warps = (long long)N;
    int blocks = (int)((warps * 32 + 255) / 256);
    k_spmm<<<blocks, 256>>>((float4*)d_out, N);
}

// round 2
// speedup vs baseline: 1.0576x; 1.0576x over previous
#include <cuda_runtime.h>
#include <cuda_fp16.h>
#include <math.h>

#define NMAX 100000
#define EMAX 1600000
#define DIN  256
#define DOUT 128

typedef unsigned long long ull;

// ---- scratch (device globals; no allocations allowed) ----
__device__ uint4 g_hh[NMAX * 16];      // h in fp16: 128 halves/row = 16 uint4 (25.6MB, L2-resident)
__device__ float g_a2[NMAX];           // s[n] = sum_c |h|*a2_w  (row-softmax key, fp32)
__device__ int   g_cnt[NMAX];          // edge histogram by row
__device__ int   g_off[NMAX + 1];      // CSR offsets
__device__ int   g_cur[NMAX];          // scatter cursors
__device__ int   g_col[EMAX];          // CSR cols
__device__ float g_val[EMAX];          // CSR signed values
__device__ int   g_bsum[128];          // scan block sums

// ---------------------------------------------------------------------------
__global__ void k_zero(int N) {
    int i = blockIdx.x * blockDim.x + threadIdx.x;
    if (i < N) g_cnt[i] = 0;
}

// ---------------------------------------------------------------------------
// f32x2 helpers
__device__ __forceinline__ ull pack2(float lo, float hi) {
    ull r;
    asm("mov.b64 %0, {%1, %2};" : "=l"(r) : "f"(lo), "f"(hi));
    return r;
}
__device__ __forceinline__ void unpack2(ull v, float& lo, float& hi) {
    asm("mov.b64 {%0, %1}, %2;" : "=f"(lo), "=f"(hi) : "l"(v));
}
__device__ __forceinline__ void fma2(ull& d, ull a, ull b) {
    asm("fma.rn.f32x2 %0, %1, %2, %0;" : "+l"(d) : "l"(a), "l"(b));
}

// ---------------------------------------------------------------------------
// GEMM: h = feat @ W + b via packed fma.rn.f32x2.
// 128 threads, tile M=64 x N=128, BK=32. Per-thread 8 rows x 8 cols
// (4 column-pairs). Fused: fp16 store of h + a2 row-reduction (fp32).
__global__ __launch_bounds__(128) void k_gemm(const float* __restrict__ feat,
                                              const float* __restrict__ W,
                                              const float* __restrict__ bias,
                                              const float* __restrict__ a2w,
                                              int N) {
    __shared__ float As[64][36];    // row-major, pad to 36 (16B-aligned rows)
    __shared__ float Bs[32][128];

    const int t    = threadIdx.x;
    const int tx   = t & 15;        // col group: cols [tx*8, tx*8+8)
    const int ty   = t >> 4;        // row group: rows [ty*8, ty*8+8)
    const int row0 = blockIdx.x * 64;

    ull acc[8][4];                  // 8 rows x 4 col-pairs
#pragma unroll
    for (int i = 0; i < 8; i++)
#pragma unroll
        for (int j = 0; j < 4; j++) acc[i][j] = 0ull;

    const float4* feat4 = (const float4*)feat;
    const float4* W4    = (const float4*)W;

    for (int k0 = 0; k0 < DIN; k0 += 32) {
        // A tile: 64x32 = 512 float4, 4 per thread
#pragma unroll
        for (int li = 0; li < 4; li++) {
            int e  = t + li * 128;
            int r  = e >> 3;
            int k4 = e & 7;
            int gr = row0 + r;
            float4 v = make_float4(0.f, 0.f, 0.f, 0.f);
            if (gr < N) v = feat4[gr * (DIN / 4) + (k0 >> 2) + k4];
            *(float4*)&As[r][k4 * 4] = v;
        }
        // B tile: 32x128 = 1024 float4, 8 per thread
#pragma unroll
        for (int li = 0; li < 8; li++) {
            int e  = t + li * 128;
            int kr = e >> 5;
            int c4 = e & 31;
            *(float4*)&Bs[kr][c4 * 4] = W4[(k0 + kr) * (DOUT / 4) + c4];
        }
        __syncthreads();

#pragma unroll 8
        for (int kk = 0; kk < 32; kk++) {
            const ull* brow = (const ull*)&Bs[kk][0];
            ull b0 = brow[tx * 4 + 0];
            ull b1 = brow[tx * 4 + 1];
            ull b2 = brow[tx * 4 + 2];
            ull b3 = brow[tx * 4 + 3];
#pragma unroll
            for (int i = 0; i < 8; i++) {
                float a = As[ty * 8 + i][kk];
                ull aa = pack2(a, a);
                fma2(acc[i][0], aa, b0);
                fma2(acc[i][1], aa, b1);
                fma2(acc[i][2], aa, b2);
                fma2(acc[i][3], aa, b3);
            }
        }
        __syncthreads();
    }

    // epilogue: +bias, fp16 store of h, fused |h|.a2_w reduction (fp32)
    float bv[8], aw[8];
#pragma unroll
    for (int j = 0; j < 8; j++) {
        bv[j] = bias[tx * 8 + j];
        aw[j] = a2w[tx * 8 + j];
    }
#pragma unroll
    for (int i = 0; i < 8; i++) {
        int gr = row0 + ty * 8 + i;
        if (gr >= N) break;
        float h[8];
#pragma unroll
        for (int j = 0; j < 4; j++) {
            unpack2(acc[i][j], h[2 * j], h[2 * j + 1]);
            h[2 * j]     += bv[2 * j];
            h[2 * j + 1] += bv[2 * j + 1];
        }
        // fp16 pack: 8 halves = one uint4
        __half2 p0 = __float22half2_rn(make_float2(h[0], h[1]));
        __half2 p1 = __float22half2_rn(make_float2(h[2], h[3]));
        __half2 p2 = __float22half2_rn(make_float2(h[4], h[5]));
        __half2 p3 = __float22half2_rn(make_float2(h[6], h[7]));
        uint4 pk;
        pk.x = *(unsigned int*)&p0;
        pk.y = *(unsigned int*)&p1;
        pk.z = *(unsigned int*)&p2;
        pk.w = *(unsigned int*)&p3;
        g_hh[gr * 16 + tx] = pk;

        float s = 0.f;
#pragma unroll
        for (int j = 0; j < 8; j++) s += fabsf(h[j]) * aw[j];
        // reduce across the 16 tx lanes (contiguous within warp half)
#pragma unroll
        for (int o = 8; o > 0; o >>= 1) s += __shfl_xor_sync(0xffffffffu, s, o);
        if (tx == 0) g_a2[gr] = s;
    }
}

// ---------------------------------------------------------------------------
__global__ void k_hist(const int* __restrict__ row, int E) {
    int e = blockIdx.x * blockDim.x + threadIdx.x;
    if (e < E) atomicAdd(&g_cnt[row[e]], 1);
}

// per-1024 block scan; local-exclusive into g_off, block totals into g_bsum
__global__ __launch_bounds__(1024) void k_scan1(int N) {
    int i    = blockIdx.x * 1024 + threadIdx.x;
    int lane = threadIdx.x & 31;
    int wid  = threadIdx.x >> 5;
    int v = (i < N) ? g_cnt[i] : 0;
    int x = v;
#pragma unroll
    for (int o = 1; o < 32; o <<= 1) {
        int y = __shfl_up_sync(0xffffffffu, x, o);
        if (lane >= o) x += y;
    }
    __shared__ int wsum[32];
    if (lane == 31) wsum[wid] = x;
    __syncthreads();
    if (wid == 0) {
        int w = wsum[lane];
#pragma unroll
        for (int o = 1; o < 32; o <<= 1) {
            int y = __shfl_up_sync(0xffffffffu, w, o);
            if (lane >= o) w += y;
        }
        wsum[lane] = w;
    }
    __syncthreads();
    int incl = x + (wid > 0 ? wsum[wid - 1] : 0);
    if (i < N) g_off[i] = incl - v;
    if (threadIdx.x == 1023) g_bsum[blockIdx.x] = incl;
}

// exclusive scan of block sums (nb <= 128)
__global__ __launch_bounds__(128) void k_scan2(int nb) {
    __shared__ int s[128];
    int t = threadIdx.x;
    int v = (t < nb) ? g_bsum[t] : 0;
    s[t] = v;
    __syncthreads();
#pragma unroll
    for (int o = 1; o < 128; o <<= 1) {
        int y = (t >= o) ? s[t - o] : 0;
        __syncthreads();
        s[t] += y;
        __syncthreads();
    }
    if (t < nb) g_bsum[t] = s[t] - v;
}

__global__ void k_scan3(int N, int E) {
    int i = blockIdx.x * blockDim.x + threadIdx.x;
    if (i < N) {
        int val = g_off[i] + g_bsum[i >> 10];
        g_off[i] = val;
        g_cur[i] = val;
    }
    if (i == 0) g_off[N] = E;
}

__global__ void k_scatter(const int* __restrict__ row, const int* __restrict__ col,
                          const float* __restrict__ values, int E) {
    int e = blockIdx.x * blockDim.x + threadIdx.x;
    if (e < E) {
        int p = atomicAdd(&g_cur[row[e]], 1);
        g_col[p] = col[e];
        g_val[p] = values[e];
    }
}

// ---------------------------------------------------------------------------
// One warp per row: softmax over edges, then attention-weighted SpMM gather
// of fp16 h[col] (uint2 = 4 halves per lane covers the 128 cols), fp32 accum.
__global__ __launch_bounds__(256) void k_spmm(float4* __restrict__ out4, int N) {
    int gw   = (blockIdx.x * blockDim.x + threadIdx.x) >> 5;
    int lane = threadIdx.x & 31;
    if (gw >= N) return;

    int base = g_off[gw];
    int end  = g_off[gw + 1];

    if (end == base) {
        out4[gw * 32 + lane] = make_float4(0.f, 0.f, 0.f, 0.f);
        return;
    }

    float m = -1e30f;
    for (int j = base + lane; j < end; j += 32)
        m = fmaxf(m, g_a2[g_col[j]]);
#pragma unroll
    for (int o = 16; o > 0; o >>= 1)
        m = fmaxf(m, __shfl_xor_sync(0xffffffffu, m, o));

    float d = 0.f;
    for (int j = base + lane; j < end; j += 32)
        d += __expf(g_a2[g_col[j]] - m);
#pragma unroll
    for (int o = 16; o > 0; o >>= 1)
        d += __shfl_xor_sync(0xffffffffu, d, o);

    const uint2* hh2 = (const uint2*)g_hh;
    float4 acc = make_float4(0.f, 0.f, 0.f, 0.f);
    for (int j = base; j < end; ++j) {
        int   c = g_col[j];                       // broadcast load
        float w = __expf(g_a2[c] - m) * g_val[j]; // broadcast loads
        uint2 hv = hh2[c * 32 + lane];            // 256B/warp gather (L2 hit)
        float2 f01 = __half22float2(*(const __half2*)&hv.x);
        float2 f23 = __half22float2(*(const __half2*)&hv.y);
        acc.x += w * f01.x;
        acc.y += w * f01.y;
        acc.z += w * f23.x;
        acc.w += w * f23.y;
    }
    float inv = 1.f / d;
    acc.x *= inv; acc.y *= inv; acc.z *= inv; acc.w *= inv;
    out4[gw * 32 + lane] = acc;
}

// ---------------------------------------------------------------------------
extern "C" void kernel_launch(void* const* d_in, const int* in_sizes, int n_in,
                              void* d_out, int out_size) {
    const float* feat   = (const float*)d_in[0];
    const float* values = (const float*)d_in[1];
    const float* W      = (const float*)d_in[2];
    const float* bias   = (const float*)d_in[3];
    // d_in[4] (a1_w), d_in[5] (a1_b), d_in[7] (a2_b) cancel in the row softmax
    const float* a2w    = (const float*)d_in[6];
    const int*   row    = (const int*)d_in[8];
    const int*   col    = (const int*)d_in[9];

    const int N = in_sizes[0] / DIN;
    const int E = in_sizes[1];

    k_zero<<<(N + 255) / 256, 256>>>(N);
    k_gemm<<<(N + 63) / 64, 128>>>(feat, W, bias, a2w, N);
    k_hist<<<(E + 255) / 256, 256>>>(row, E);

    int nb = (N + 1023) / 1024;
    k_scan1<<<nb, 1024>>>(N);
    k_scan2<<<1, 128>>>(nb);
    k_scan3<<<(N + 255) / 256, 256>>>(N, E);
    k_scatter<<<(E + 255) / 256, 256>>>(row, col, values, E);

    long long warps = (long long)N;
    int blocks = (int)((warps * 32 + 255) / 256);
    k_spmm<<<blocks, 256>>>((float4*)d_out, N);
}

// round 4
// speedup vs baseline: 1.3931x; 1.3171x over previous
#include <cuda_runtime.h>
#include <cuda_fp16.h>
#include <cuda_bf16.h>
#include <math.h>

#define NMAX 100000
#define EMAX 1600000
#define DIN  256
#define DOUT 128

// ---- scratch (device globals; no allocations allowed) ----
__device__ uint4 g_hh[NMAX * 16];      // h in fp16: 128 halves/row (25.6MB, L2-resident)
__device__ float g_a2[NMAX];           // softmax key: sum_c |h|*a2_w
__device__ int   g_cnt[NMAX];
__device__ int   g_off[NMAX + 1];
__device__ int   g_cur[NMAX];
__device__ int   g_col[EMAX];
__device__ float g_val[EMAX];
__device__ int   g_bsum[128];
__device__ __nv_bfloat16 g_wh[DOUT * DIN];   // W^T [n][k] bf16 hi
__device__ __nv_bfloat16 g_wl[DOUT * DIN];   // W^T [n][k] bf16 lo

// ---------------------------------------------------------------------------
__global__ void k_zero(int N) {
    int i = blockIdx.x * blockDim.x + threadIdx.x;
    if (i < N) g_cnt[i] = 0;
}

// W [k][n] fp32 -> W^T hi/lo bf16 [n][k]
__global__ void k_wconv(const float* __restrict__ W) {
    int i = blockIdx.x * blockDim.x + threadIdx.x;
    if (i < DIN * DOUT) {
        int k = i >> 7, n = i & 127;
        float x = W[i];
        __nv_bfloat16 h = __float2bfloat16(x);
        __nv_bfloat16 l = __float2bfloat16(x - __bfloat162float(h));
        g_wh[n * DIN + k] = h;
        g_wl[n * DIN + k] = l;
    }
}

// ---------------------------------------------------------------------------
// HMMA split-bf16 GEMM: h = feat @ W + b (3-pass hi/lo, fp32 accum).
// CTA: 256 thr, tile M=128 x N=128; warp tile 32x64 (warps 4M x 2N).
// K chunked by 64 through padded smem (stride 72 bf16 -> conflict-free LDS).
// Fused epilogue: +bias, fp16 h store, a2 row-reduction via smem atomics.

#define PAD 72                          // smem row stride in bf16 elements
#define OFF_CONST 0                     // bias[128] + a2w[128]
#define OFF_AH    1024
#define OFF_AL    (OFF_AH + 128 * PAD * 2)
#define OFF_BH    (OFF_AL + 128 * PAD * 2)
#define OFF_BL    (OFF_BH + 128 * PAD * 2)
#define SMEM_DYN  (OFF_BL + 128 * PAD * 2)

__device__ __forceinline__ void mma16816(float* d, const unsigned* a,
                                         const unsigned* b) {
    asm volatile(
        "mma.sync.aligned.m16n8k16.row.col.f32.bf16.bf16.f32 "
        "{%0,%1,%2,%3}, {%4,%5,%6,%7}, {%8,%9}, {%0,%1,%2,%3};"
        : "+f"(d[0]), "+f"(d[1]), "+f"(d[2]), "+f"(d[3])
        : "r"(a[0]), "r"(a[1]), "r"(a[2]), "r"(a[3]), "r"(b[0]), "r"(b[1]));
}

__global__ __launch_bounds__(256, 2) void k_gemm(const float* __restrict__ feat,
                                                 const float* __restrict__ bias,
                                                 const float* __restrict__ a2w,
                                                 int N) {
    extern __shared__ char smem[];
    __nv_bfloat16* AH = (__nv_bfloat16*)(smem + OFF_AH);
    __nv_bfloat16* AL = (__nv_bfloat16*)(smem + OFF_AL);
    __nv_bfloat16* BH = (__nv_bfloat16*)(smem + OFF_BH);
    __nv_bfloat16* BL = (__nv_bfloat16*)(smem + OFF_BL);
    float* sb = (float*)(smem + OFF_CONST);        // bias
    float* sa = sb + 128;                          // a2w

    const int t     = threadIdx.x;
    const int lane  = t & 31;
    const int wid   = t >> 5;
    const int warpM = wid & 3;
    const int warpN = wid >> 2;
    const int r0    = blockIdx.x * 128;
    const int q2    = (lane & 3) << 1;             // k/col pair base
    const int g4    = lane >> 2;                   // row/n group

    if (t < 128) { sb[t] = bias[t]; sa[t] = a2w[t]; }

    float acc[2][8][4];
#pragma unroll
    for (int mf = 0; mf < 2; mf++)
#pragma unroll
        for (int nf = 0; nf < 8; nf++)
#pragma unroll
            for (int j = 0; j < 4; j++) acc[mf][nf][j] = 0.f;

    const float4* feat4 = (const float4*)feat;
    const uint4*  wh4   = (const uint4*)g_wh;
    const uint4*  wl4   = (const uint4*)g_wl;

    for (int kc = 0; kc < 4; kc++) {
        // --- A chunk: 128 rows x 64 fp32 -> bf16 hi/lo, padded smem ---
#pragma unroll
        for (int i = 0; i < 4; i++) {
            int seg = t + i * 256;          // 1024 segs of 8 floats
            int row = seg >> 3;
            int k8  = seg & 7;
            int gr  = r0 + row;
            float4 f0 = make_float4(0.f, 0.f, 0.f, 0.f), f1 = f0;
            if (gr < N) {
                f0 = feat4[gr * 64 + kc * 16 + k8 * 2 + 0];
                f1 = feat4[gr * 64 + kc * 16 + k8 * 2 + 1];
            }
            float x[8] = {f0.x, f0.y, f0.z, f0.w, f1.x, f1.y, f1.z, f1.w};
            __nv_bfloat16 hb[8], lb[8];
#pragma unroll
            for (int j = 0; j < 8; j++) {
                hb[j] = __float2bfloat16(x[j]);
                lb[j] = __float2bfloat16(x[j] - __bfloat162float(hb[j]));
            }
            *(uint4*)&AH[row * PAD + k8 * 8] = *(const uint4*)hb;
            *(uint4*)&AL[row * PAD + k8 * 8] = *(const uint4*)lb;
        }
        // --- B chunk: 128 n-rows x 64 bf16 hi/lo ---
#pragma unroll
        for (int i = 0; i < 4; i++) {
            int seg = t + i * 256;
            int n   = seg >> 3;
            int k8  = seg & 7;
            *(uint4*)&BH[n * PAD + k8 * 8] = wh4[n * 32 + kc * 8 + k8];
            *(uint4*)&BL[n * PAD + k8 * 8] = wl4[n * 32 + kc * 8 + k8];
        }
        __syncthreads();

#pragma unroll
        for (int ks = 0; ks < 4; ks++) {
            const int ak = ks * 16 + q2;
            unsigned ah[2][4], al[2][4];
#pragma unroll
            for (int mf = 0; mf < 2; mf++) {
                int ar = warpM * 32 + mf * 16 + g4;
                ah[mf][0] = *(const unsigned*)&AH[ar * PAD + ak];
                ah[mf][1] = *(const unsigned*)&AH[(ar + 8) * PAD + ak];
                ah[mf][2] = *(const unsigned*)&AH[ar * PAD + ak + 8];
                ah[mf][3] = *(const unsigned*)&AH[(ar + 8) * PAD + ak + 8];
                al[mf][0] = *(const unsigned*)&AL[ar * PAD + ak];
                al[mf][1] = *(const unsigned*)&AL[(ar + 8) * PAD + ak];
                al[mf][2] = *(const unsigned*)&AL[ar * PAD + ak + 8];
                al[mf][3] = *(const unsigned*)&AL[(ar + 8) * PAD + ak + 8];
            }
#pragma unroll
            for (int nf = 0; nf < 8; nf++) {
                int bn = warpN * 64 + nf * 8 + g4;
                unsigned bh[2], bl[2];
                bh[0] = *(const unsigned*)&BH[bn * PAD + ak];
                bh[1] = *(const unsigned*)&BH[bn * PAD + ak + 8];
                bl[0] = *(const unsigned*)&BL[bn * PAD + ak];
                bl[1] = *(const unsigned*)&BL[bn * PAD + ak + 8];
#pragma unroll
                for (int mf = 0; mf < 2; mf++) {
                    mma16816(acc[mf][nf], ah[mf], bh);
                    mma16816(acc[mf][nf], ah[mf], bl);
                    mma16816(acc[mf][nf], al[mf], bh);
                }
            }
        }
        __syncthreads();
    }

    // --- epilogue ---
    float* a2s = (float*)(smem + OFF_AH);   // reuse tile smem (post-sync)
    if (t < 128) a2s[t] = 0.f;
    __syncthreads();

    __half2* hh = (__half2*)g_hh;
#pragma unroll
    for (int mf = 0; mf < 2; mf++) {
        int rl = warpM * 32 + mf * 16 + g4;
        int rh = rl + 8;
        float s0 = 0.f, s1 = 0.f;
#pragma unroll
        for (int nf = 0; nf < 8; nf++) {
            int c = warpN * 64 + nf * 8 + q2;
            float b0 = sb[c], b1 = sb[c + 1];
            float w0 = sa[c], w1 = sa[c + 1];
            float h0 = acc[mf][nf][0] + b0, h1 = acc[mf][nf][1] + b1;
            float h2 = acc[mf][nf][2] + b0, h3 = acc[mf][nf][3] + b1;
            if (r0 + rl < N) hh[(long)(r0 + rl) * 64 + (c >> 1)] = __floats2half2_rn(h0, h1);
            if (r0 + rh < N) hh[(long)(r0 + rh) * 64 + (c >> 1)] = __floats2half2_rn(h2, h3);
            s0 += fabsf(h0) * w0 + fabsf(h1) * w1;
            s1 += fabsf(h2) * w0 + fabsf(h3) * w1;
        }
        atomicAdd(&a2s[rl], s0);
        atomicAdd(&a2s[rh], s1);
    }
    __syncthreads();
    if (t < 128 && r0 + t < N) g_a2[r0 + t] = a2s[t];
}

// ---------------------------------------------------------------------------
__global__ void k_hist(const int* __restrict__ row, int E) {
    int e = blockIdx.x * blockDim.x + threadIdx.x;
    if (e < E) atomicAdd(&g_cnt[row[e]], 1);
}

__global__ __launch_bounds__(1024) void k_scan1(int N) {
    int i    = blockIdx.x * 1024 + threadIdx.x;
    int lane = threadIdx.x & 31;
    int wid  = threadIdx.x >> 5;
    int v = (i < N) ? g_cnt[i] : 0;
    int x = v;
#pragma unroll
    for (int o = 1; o < 32; o <<= 1) {
        int y = __shfl_up_sync(0xffffffffu, x, o);
        if (lane >= o) x += y;
    }
    __shared__ int wsum[32];
    if (lane == 31) wsum[wid] = x;
    __syncthreads();
    if (wid == 0) {
        int w = wsum[lane];
#pragma unroll
        for (int o = 1; o < 32; o <<= 1) {
            int y = __shfl_up_sync(0xffffffffu, w, o);
            if (lane >= o) w += y;
        }
        wsum[lane] = w;
    }
    __syncthreads();
    int incl = x + (wid > 0 ? wsum[wid - 1] : 0);
    if (i < N) g_off[i] = incl - v;
    if (threadIdx.x == 1023) g_bsum[blockIdx.x] = incl;
}

__global__ __launch_bounds__(128) void k_scan2(int nb) {
    __shared__ int s[128];
    int t = threadIdx.x;
    int v = (t < nb) ? g_bsum[t] : 0;
    s[t] = v;
    __syncthreads();
#pragma unroll
    for (int o = 1; o < 128; o <<= 1) {
        int y = (t >= o) ? s[t - o] : 0;
        __syncthreads();
        s[t] += y;
        __syncthreads();
    }
    if (t < nb) g_bsum[t] = s[t] - v;
}

__global__ void k_scan3(int N, int E) {
    int i = blockIdx.x * blockDim.x + threadIdx.x;
    if (i < N) {
        int val = g_off[i] + g_bsum[i >> 10];
        g_off[i] = val;
        g_cur[i] = val;
    }
    if (i == 0) g_off[N] = E;
}

__global__ void k_scatter(const int* __restrict__ row, const int* __restrict__ col,
                          const float* __restrict__ values, int E) {
    int e = blockIdx.x * blockDim.x + threadIdx.x;
    if (e < E) {
        int p = atomicAdd(&g_cur[row[e]], 1);
        g_col[p] = col[e];
        g_val[p] = values[e];
    }
}

// ---------------------------------------------------------------------------
// One warp per row: softmax over edges, attention-weighted SpMM of fp16 h.
__global__ __launch_bounds__(256) void k_spmm(float4* __restrict__ out4, int N) {
    int gw   = (blockIdx.x * blockDim.x + threadIdx.x) >> 5;
    int lane = threadIdx.x & 31;
    if (gw >= N) return;

    int base = g_off[gw];
    int end  = g_off[gw + 1];

    if (end == base) {
        out4[gw * 32 + lane] = make_float4(0.f, 0.f, 0.f, 0.f);
        return;
    }

    float m = -1e30f;
    for (int j = base + lane; j < end; j += 32)
        m = fmaxf(m, g_a2[g_col[j]]);
#pragma unroll
    for (int o = 16; o > 0; o >>= 1)
        m = fmaxf(m, __shfl_xor_sync(0xffffffffu, m, o));

    float d = 0.f;
    for (int j = base + lane; j < end; j += 32)
        d += __expf(g_a2[g_col[j]] - m);
#pragma unroll
    for (int o = 16; o > 0; o >>= 1)
        d += __shfl_xor_sync(0xffffffffu, d, o);

    const uint2* hh2 = (const uint2*)g_hh;
    float4 acc = make_float4(0.f, 0.f, 0.f, 0.f);
    for (int j = base; j < end; ++j) {
        int   c = g_col[j];
        float w = __expf(g_a2[c] - m) * g_val[j];
        uint2 hv = hh2[c * 32 + lane];
        float2 f01 = __half22float2(*(const __half2*)&hv.x);
        float2 f23 = __half22float2(*(const __half2*)&hv.y);
        acc.x += w * f01.x;
        acc.y += w * f01.y;
        acc.z += w * f23.x;
        acc.w += w * f23.y;
    }
    float inv = 1.f / d;
    acc.x *= inv; acc.y *= inv; acc.z *= inv; acc.w *= inv;
    out4[gw * 32 + lane] = acc;
}

// ---------------------------------------------------------------------------
extern "C" void kernel_launch(void* const* d_in, const int* in_sizes, int n_in,
                              void* d_out, int out_size) {
    const float* feat   = (const float*)d_in[0];
    const float* values = (const float*)d_in[1];
    const float* W      = (const float*)d_in[2];
    const float* bias   = (const float*)d_in[3];
    const float* a2w    = (const float*)d_in[6];   // a1 terms cancel in row-softmax
    const int*   row    = (const int*)d_in[8];
    const int*   col    = (const int*)d_in[9];

    const int N = in_sizes[0] / DIN;
    const int E = in_sizes[1];

    cudaFuncSetAttribute(k_gemm, cudaFuncAttributeMaxDynamicSharedMemorySize,
                         SMEM_DYN);

    int nb = (N + 1023) / 1024;

    k_zero<<<(N + 255) / 256, 256>>>(N);
    k_wconv<<<(DIN * DOUT + 255) / 256, 256>>>(W);
    k_hist<<<(E + 255) / 256, 256>>>(row, E);
    k_scan1<<<nb, 1024>>>(N);
    k_scan2<<<1, 128>>>(nb);
    k_gemm<<<(N + 127) / 128, 256, SMEM_DYN>>>(feat, bias, a2w, N);
    k_scan3<<<(N + 255) / 256, 256>>>(N, E);
    k_scatter<<<(E + 255) / 256, 256>>>(row, col, values, E);

    long long warps = (long long)N;
    int blocks = (int)((warps * 32 + 255) / 256);
    k_spmm<<<blocks, 256>>>((float4*)d_out, N);
}

// round 5
// speedup vs baseline: 1.6212x; 1.1638x over previous
#include <cuda_runtime.h>
#include <cuda_fp16.h>
#include <math.h>

#define NMAX 100000
#define EMAX 1600000
#define DIN  256
#define DOUT 128

// ---- scratch (device globals; no allocations allowed) ----
__device__ uint4 g_hh[NMAX * 16];      // h in fp16: 128 halves/row (25.6MB, L2-resident)
__device__ float g_a2[NMAX];           // softmax key: sum_c |h|*a2_w
__device__ int   g_cnt[NMAX];
__device__ int   g_off[NMAX + 1];
__device__ int   g_cur[NMAX];
__device__ int   g_col[EMAX];
__device__ float g_val[EMAX];
__device__ int   g_bsum[128];
__device__ __half g_wt[DOUT * DIN];    // W^T [n][k] fp16

// ---------------------------------------------------------------------------
__global__ void k_zero(int N) {
    int i = blockIdx.x * blockDim.x + threadIdx.x;
    if (i < N) g_cnt[i] = 0;
}

// W [k][n] fp32 -> W^T fp16 [n][k]
__global__ void k_wconv(const float* __restrict__ W) {
    int i = blockIdx.x * blockDim.x + threadIdx.x;
    if (i < DIN * DOUT) {
        int k = i >> 7, n = i & 127;
        g_wt[n * DIN + k] = __float2half_rn(W[i]);
    }
}

// ---------------------------------------------------------------------------
// HMMA fp16 GEMM: h = feat @ W + b (single pass, fp32 accum).
// CTA: 256 thr, tile M=128 x N=128; warp tile 32x64 (warps 4M x 2N).
// K chunked by 64 through padded smem (stride 72 halves, conflict-free LDS).
// Fused epilogue: +bias, fp16 h store, a2 row-reduction via smem atomics.

#define PAD 72
#define OFF_CONST 0                     // bias[128] + a2w[128]
#define OFF_A     1024
#define OFF_B     (OFF_A + 128 * PAD * 2)
#define SMEM_DYN  (OFF_B + 128 * PAD * 2)

__device__ __forceinline__ void mma16816(float* d, const unsigned* a,
                                         const unsigned* b) {
    asm volatile(
        "mma.sync.aligned.m16n8k16.row.col.f32.f16.f16.f32 "
        "{%0,%1,%2,%3}, {%4,%5,%6,%7}, {%8,%9}, {%0,%1,%2,%3};"
        : "+f"(d[0]), "+f"(d[1]), "+f"(d[2]), "+f"(d[3])
        : "r"(a[0]), "r"(a[1]), "r"(a[2]), "r"(a[3]), "r"(b[0]), "r"(b[1]));
}

__global__ __launch_bounds__(256, 2) void k_gemm(const float* __restrict__ feat,
                                                 const float* __restrict__ bias,
                                                 const float* __restrict__ a2w,
                                                 int N) {
    extern __shared__ char smem[];
    __half* A = (__half*)(smem + OFF_A);
    __half* B = (__half*)(smem + OFF_B);
    float* sb = (float*)(smem + OFF_CONST);
    float* sa = sb + 128;

    const int t     = threadIdx.x;
    const int lane  = t & 31;
    const int wid   = t >> 5;
    const int warpM = wid & 3;
    const int warpN = wid >> 2;
    const int r0    = blockIdx.x * 128;
    const int q2    = (lane & 3) << 1;
    const int g4    = lane >> 2;

    if (t < 128) { sb[t] = bias[t]; sa[t] = a2w[t]; }

    float acc[2][8][4];
#pragma unroll
    for (int mf = 0; mf < 2; mf++)
#pragma unroll
        for (int nf = 0; nf < 8; nf++)
#pragma unroll
            for (int j = 0; j < 4; j++) acc[mf][nf][j] = 0.f;

    const float4* feat4 = (const float4*)feat;
    const uint4*  wt4   = (const uint4*)g_wt;

    for (int kc = 0; kc < 4; kc++) {
        // --- A chunk: 128 rows x 64 fp32 -> fp16, padded smem ---
#pragma unroll
        for (int i = 0; i < 4; i++) {
            int seg = t + i * 256;          // 1024 segs of 8 floats
            int row = seg >> 3;
            int k8  = seg & 7;
            int gr  = r0 + row;
            float4 f0 = make_float4(0.f, 0.f, 0.f, 0.f), f1 = f0;
            if (gr < N) {
                f0 = feat4[gr * 64 + kc * 16 + k8 * 2 + 0];
                f1 = feat4[gr * 64 + kc * 16 + k8 * 2 + 1];
            }
            __half hb[8];
            hb[0] = __float2half_rn(f0.x); hb[1] = __float2half_rn(f0.y);
            hb[2] = __float2half_rn(f0.z); hb[3] = __float2half_rn(f0.w);
            hb[4] = __float2half_rn(f1.x); hb[5] = __float2half_rn(f1.y);
            hb[6] = __float2half_rn(f1.z); hb[7] = __float2half_rn(f1.w);
            *(uint4*)&A[row * PAD + k8 * 8] = *(const uint4*)hb;
        }
        // --- B chunk: 128 n-rows x 64 fp16 ---
#pragma unroll
        for (int i = 0; i < 4; i++) {
            int seg = t + i * 256;
            int n   = seg >> 3;
            int k8  = seg & 7;
            *(uint4*)&B[n * PAD + k8 * 8] = wt4[n * 32 + kc * 8 + k8];
        }
        __syncthreads();

#pragma unroll
        for (int ks = 0; ks < 4; ks++) {
            const int ak = ks * 16 + q2;
            unsigned ar_[2][4];
#pragma unroll
            for (int mf = 0; mf < 2; mf++) {
                int ar = warpM * 32 + mf * 16 + g4;
                ar_[mf][0] = *(const unsigned*)&A[ar * PAD + ak];
                ar_[mf][1] = *(const unsigned*)&A[(ar + 8) * PAD + ak];
                ar_[mf][2] = *(const unsigned*)&A[ar * PAD + ak + 8];
                ar_[mf][3] = *(const unsigned*)&A[(ar + 8) * PAD + ak + 8];
            }
#pragma unroll
            for (int nf = 0; nf < 8; nf++) {
                int bn = warpN * 64 + nf * 8 + g4;
                unsigned br[2];
                br[0] = *(const unsigned*)&B[bn * PAD + ak];
                br[1] = *(const unsigned*)&B[bn * PAD + ak + 8];
                mma16816(acc[0][nf], ar_[0], br);
                mma16816(acc[1][nf], ar_[1], br);
            }
        }
        __syncthreads();
    }

    // --- epilogue ---
    float* a2s = (float*)(smem + OFF_A);    // reuse tile smem (post-sync)
    if (t < 128) a2s[t] = 0.f;
    __syncthreads();

    __half2* hh = (__half2*)g_hh;
#pragma unroll
    for (int mf = 0; mf < 2; mf++) {
        int rl = warpM * 32 + mf * 16 + g4;
        int rh = rl + 8;
        float s0 = 0.f, s1 = 0.f;
#pragma unroll
        for (int nf = 0; nf < 8; nf++) {
            int c = warpN * 64 + nf * 8 + q2;
            float b0 = sb[c], b1 = sb[c + 1];
            float w0 = sa[c], w1 = sa[c + 1];
            float h0 = acc[mf][nf][0] + b0, h1 = acc[mf][nf][1] + b1;
            float h2 = acc[mf][nf][2] + b0, h3 = acc[mf][nf][3] + b1;
            if (r0 + rl < N) hh[(long)(r0 + rl) * 64 + (c >> 1)] = __floats2half2_rn(h0, h1);
            if (r0 + rh < N) hh[(long)(r0 + rh) * 64 + (c >> 1)] = __floats2half2_rn(h2, h3);
            s0 += fabsf(h0) * w0 + fabsf(h1) * w1;
            s1 += fabsf(h2) * w0 + fabsf(h3) * w1;
        }
        atomicAdd(&a2s[rl], s0);
        atomicAdd(&a2s[rh], s1);
    }
    __syncthreads();
    if (t < 128 && r0 + t < N) g_a2[r0 + t] = a2s[t];
}

// ---------------------------------------------------------------------------
__global__ void k_hist(const int* __restrict__ row, int E) {
    int e = blockIdx.x * blockDim.x + threadIdx.x;
    if (e < E) atomicAdd(&g_cnt[row[e]], 1);
}

__global__ __launch_bounds__(1024) void k_scan1(int N) {
    int i    = blockIdx.x * 1024 + threadIdx.x;
    int lane = threadIdx.x & 31;
    int wid  = threadIdx.x >> 5;
    int v = (i < N) ? g_cnt[i] : 0;
    int x = v;
#pragma unroll
    for (int o = 1; o < 32; o <<= 1) {
        int y = __shfl_up_sync(0xffffffffu, x, o);
        if (lane >= o) x += y;
    }
    __shared__ int wsum[32];
    if (lane == 31) wsum[wid] = x;
    __syncthreads();
    if (wid == 0) {
        int w = wsum[lane];
#pragma unroll
        for (int o = 1; o < 32; o <<= 1) {
            int y = __shfl_up_sync(0xffffffffu, w, o);
            if (lane >= o) w += y;
        }
        wsum[lane] = w;
    }
    __syncthreads();
    int incl = x + (wid > 0 ? wsum[wid - 1] : 0);
    if (i < N) g_off[i] = incl - v;
    if (threadIdx.x == 1023) g_bsum[blockIdx.x] = incl;
}

__global__ __launch_bounds__(128) void k_scan2(int nb) {
    __shared__ int s[128];
    int t = threadIdx.x;
    int v = (t < nb) ? g_bsum[t] : 0;
    s[t] = v;
    __syncthreads();
#pragma unroll
    for (int o = 1; o < 128; o <<= 1) {
        int y = (t >= o) ? s[t - o] : 0;
        __syncthreads();
        s[t] += y;
        __syncthreads();
    }
    if (t < nb) g_bsum[t] = s[t] - v;
}

__global__ void k_scan3(int N, int E) {
    int i = blockIdx.x * blockDim.x + threadIdx.x;
    if (i < N) {
        int val = g_off[i] + g_bsum[i >> 10];
        g_off[i] = val;
        g_cur[i] = val;
    }
    if (i == 0) g_off[N] = E;
}

__global__ void k_scatter(const int* __restrict__ row, const int* __restrict__ col,
                          const float* __restrict__ values, int E) {
    int e = blockIdx.x * blockDim.x + threadIdx.x;
    if (e < E) {
        int p = atomicAdd(&g_cur[row[e]], 1);
        g_col[p] = col[e];
        g_val[p] = values[e];
    }
}

// ---------------------------------------------------------------------------
// One warp per row: softmax over edges, attention-weighted SpMM of fp16 h.
__global__ __launch_bounds__(256) void k_spmm(float4* __restrict__ out4, int N) {
    int gw   = (blockIdx.x * blockDim.x + threadIdx.x) >> 5;
    int lane = threadIdx.x & 31;
    if (gw >= N) return;

    int base = g_off[gw];
    int end  = g_off[gw + 1];

    if (end == base) {
        out4[gw * 32 + lane] = make_float4(0.f, 0.f, 0.f, 0.f);
        return;
    }

    float m = -1e30f;
    for (int j = base + lane; j < end; j += 32)
        m = fmaxf(m, g_a2[g_col[j]]);
#pragma unroll
    for (int o = 16; o > 0; o >>= 1)
        m = fmaxf(m, __shfl_xor_sync(0xffffffffu, m, o));

    float d = 0.f;
    for (int j = base + lane; j < end; j += 32)
        d += __expf(g_a2[g_col[j]] - m);
#pragma unroll
    for (int o = 16; o > 0; o >>= 1)
        d += __shfl_xor_sync(0xffffffffu, d, o);

    const uint2* hh2 = (const uint2*)g_hh;
    float4 acc = make_float4(0.f, 0.f, 0.f, 0.f);
    for (int j = base; j < end; ++j) {
        int   c = g_col[j];
        float w = __expf(g_a2[c] - m) * g_val[j];
        uint2 hv = hh2[c * 32 + lane];
        float2 f01 = __half22float2(*(const __half2*)&hv.x);
        float2 f23 = __half22float2(*(const __half2*)&hv.y);
        acc.x += w * f01.x;
        acc.y += w * f01.y;
        acc.z += w * f23.x;
        acc.w += w * f23.y;
    }
    float inv = 1.f / d;
    acc.x *= inv; acc.y *= inv; acc.z *= inv; acc.w *= inv;
    out4[gw * 32 + lane] = acc;
}

// ---------------------------------------------------------------------------
extern "C" void kernel_launch(void* const* d_in, const int* in_sizes, int n_in,
                              void* d_out, int out_size) {
    const float* feat   = (const float*)d_in[0];
    const float* values = (const float*)d_in[1];
    const float* W      = (const float*)d_in[2];
    const float* bias   = (const float*)d_in[3];
    const float* a2w    = (const float*)d_in[6];   // a1 terms cancel in row-softmax
    const int*   row    = (const int*)d_in[8];
    const int*   col    = (const int*)d_in[9];

    const int N = in_sizes[0] / DIN;
    const int E = in_sizes[1];

    cudaFuncSetAttribute(k_gemm, cudaFuncAttributeMaxDynamicSharedMemorySize,
                         SMEM_DYN);

    int nb = (N + 1023) / 1024;

    k_zero<<<(N + 255) / 256, 256>>>(N);
    k_wconv<<<(DIN * DOUT + 255) / 256, 256>>>(W);
    k_hist<<<(E + 255) / 256, 256>>>(row, E);
    k_scan1<<<nb, 1024>>>(N);
    k_scan2<<<1, 128>>>(nb);
    k_gemm<<<(N + 127) / 128, 256, SMEM_DYN>>>(feat, bias, a2w, N);
    k_scan3<<<(N + 255) / 256, 256>>>(N, E);
    k_scatter<<<(E + 255) / 256, 256>>>(row, col, values, E);

    long long warps = (long long)N;
    int blocks = (int)((warps * 32 + 255) / 256);
    k_spmm<<<blocks, 256>>>((float4*)d_out, N);
}

// round 6
// speedup vs baseline: 1.9714x; 1.2160x over previous
#include <cuda_runtime.h>
#include <cuda_fp16.h>
#include <math.h>

#define NMAX 100000
#define EMAX 1600000
#define DIN  256
#define DOUT 128

// ---- scratch (device globals; no allocations allowed) ----
__device__ uint4 g_hh[NMAX * 16];      // h in fp16: 128 halves/row (25.6MB, L2-resident)
__device__ float g_e[NMAX];            // e[n] = exp(sum_c |h|*a2_w)  (softmax numerator)
__device__ int   g_cnt[NMAX];
__device__ int   g_off[NMAX + 1];
__device__ int   g_cur[NMAX];
__device__ unsigned g_col[EMAX];       // CSR col, bit31 = sign(value)
__device__ int   g_bsum[128];
__device__ __half g_wt[DOUT * DIN];    // W^T [n][k] fp16

// ---------------------------------------------------------------------------
__global__ void k_zero(int N) {
    int i = blockIdx.x * blockDim.x + threadIdx.x;
    if (i < N) g_cnt[i] = 0;
}

// W [k][n] fp32 -> W^T fp16 [n][k]
__global__ void k_wconv(const float* __restrict__ W) {
    int i = blockIdx.x * blockDim.x + threadIdx.x;
    if (i < DIN * DOUT) {
        int k = i >> 7, n = i & 127;
        g_wt[n * DIN + k] = __float2half_rn(W[i]);
    }
}

// ---------------------------------------------------------------------------
// HMMA fp16 GEMM, double-buffered: h = feat @ W + b (fp32 accum).
// CTA: 256 thr, tile M=128 x N=128; warp tile 32x64. K chunked by 64,
// 2-stage smem pipeline (global loads overlap MMA). Fused epilogue:
// +bias, fp16 h store, e = exp(sum |h|*a2_w) via smem atomics.

#define PAD 72
#define OFF_CONST 0                     // bias[128] + a2w[128]
#define STAGE_BYTES (128 * PAD * 2)
#define OFF_A0    1024
#define OFF_B0    (OFF_A0 + STAGE_BYTES)
#define OFF_A1    (OFF_B0 + STAGE_BYTES)
#define OFF_B1    (OFF_A1 + STAGE_BYTES)
#define SMEM_DYN  (OFF_B1 + STAGE_BYTES)

__device__ __forceinline__ void mma16816(float* d, const unsigned* a,
                                         const unsigned* b) {
    asm volatile(
        "mma.sync.aligned.m16n8k16.row.col.f32.f16.f16.f32 "
        "{%0,%1,%2,%3}, {%4,%5,%6,%7}, {%8,%9}, {%0,%1,%2,%3};"
        : "+f"(d[0]), "+f"(d[1]), "+f"(d[2]), "+f"(d[3])
        : "r"(a[0]), "r"(a[1]), "r"(a[2]), "r"(a[3]), "r"(b[0]), "r"(b[1]));
}

__global__ __launch_bounds__(256, 2) void k_gemm(const float* __restrict__ feat,
                                                 const float* __restrict__ bias,
                                                 const float* __restrict__ a2w,
                                                 int N) {
    extern __shared__ char smem[];
    float* sb = (float*)(smem + OFF_CONST);
    float* sa = sb + 128;

    const int t     = threadIdx.x;
    const int lane  = t & 31;
    const int wid   = t >> 5;
    const int warpM = wid & 3;
    const int warpN = wid >> 2;
    const int r0    = blockIdx.x * 128;
    const int q2    = (lane & 3) << 1;
    const int g4    = lane >> 2;

    if (t < 128) { sb[t] = bias[t]; sa[t] = a2w[t]; }

    float acc[2][8][4];
#pragma unroll
    for (int mf = 0; mf < 2; mf++)
#pragma unroll
        for (int nf = 0; nf < 8; nf++)
#pragma unroll
            for (int j = 0; j < 4; j++) acc[mf][nf][j] = 0.f;

    const float4* feat4 = (const float4*)feat;
    const uint4*  wt4   = (const uint4*)g_wt;

    // per-thread load geometry (4 segs of 8 elements each, per chunk)
    int arow[4], ak8[4];
#pragma unroll
    for (int i = 0; i < 4; i++) {
        int seg = t + i * 256;
        arow[i] = seg >> 3;
        ak8[i]  = seg & 7;
    }

    uint4 aReg[4], bReg[4];

    // ld: global -> regs (A converted to fp16 in regs)
    auto ldchunk = [&](int kc) {
#pragma unroll
        for (int i = 0; i < 4; i++) {
            int gr = r0 + arow[i];
            float4 f0 = make_float4(0.f, 0.f, 0.f, 0.f), f1 = f0;
            if (gr < N) {
                f0 = feat4[gr * 64 + kc * 16 + ak8[i] * 2 + 0];
                f1 = feat4[gr * 64 + kc * 16 + ak8[i] * 2 + 1];
            }
            __half hb[8];
            hb[0] = __float2half_rn(f0.x); hb[1] = __float2half_rn(f0.y);
            hb[2] = __float2half_rn(f0.z); hb[3] = __float2half_rn(f0.w);
            hb[4] = __float2half_rn(f1.x); hb[5] = __float2half_rn(f1.y);
            hb[6] = __float2half_rn(f1.z); hb[7] = __float2half_rn(f1.w);
            aReg[i] = *(const uint4*)hb;
            bReg[i] = wt4[arow[i] * 32 + kc * 8 + ak8[i]];
        }
    };
    // st: regs -> smem stage
    auto stchunk = [&](int stg) {
        __half* A = (__half*)(smem + (stg ? OFF_A1 : OFF_A0));
        __half* B = (__half*)(smem + (stg ? OFF_B1 : OFF_B0));
#pragma unroll
        for (int i = 0; i < 4; i++) {
            *(uint4*)&A[arow[i] * PAD + ak8[i] * 8] = aReg[i];
            *(uint4*)&B[arow[i] * PAD + ak8[i] * 8] = bReg[i];
        }
    };

    ldchunk(0);
    stchunk(0);
    __syncthreads();

    for (int kc = 0; kc < 4; kc++) {
        if (kc < 3) ldchunk(kc + 1);            // overlap with MMA below

        const __half* A = (const __half*)(smem + ((kc & 1) ? OFF_A1 : OFF_A0));
        const __half* B = (const __half*)(smem + ((kc & 1) ? OFF_B1 : OFF_B0));
#pragma unroll
        for (int ks = 0; ks < 4; ks++) {
            const int ak = ks * 16 + q2;
            unsigned ar_[2][4];
#pragma unroll
            for (int mf = 0; mf < 2; mf++) {
                int ar = warpM * 32 + mf * 16 + g4;
                ar_[mf][0] = *(const unsigned*)&A[ar * PAD + ak];
                ar_[mf][1] = *(const unsigned*)&A[(ar + 8) * PAD + ak];
                ar_[mf][2] = *(const unsigned*)&A[ar * PAD + ak + 8];
                ar_[mf][3] = *(const unsigned*)&A[(ar + 8) * PAD + ak + 8];
            }
#pragma unroll
            for (int nf = 0; nf < 8; nf++) {
                int bn = warpN * 64 + nf * 8 + g4;
                unsigned br[2];
                br[0] = *(const unsigned*)&B[bn * PAD + ak];
                br[1] = *(const unsigned*)&B[bn * PAD + ak + 8];
                mma16816(acc[0][nf], ar_[0], br);
                mma16816(acc[1][nf], ar_[1], br);
            }
        }
        __syncthreads();
        if (kc < 3) {
            stchunk((kc + 1) & 1);
            __syncthreads();
        }
    }

    // --- epilogue ---
    float* a2s = (float*)(smem + OFF_A0);   // reuse tile smem (post-sync)
    if (t < 128) a2s[t] = 0.f;
    __syncthreads();

    __half2* hh = (__half2*)g_hh;
#pragma unroll
    for (int mf = 0; mf < 2; mf++) {
        int rl = warpM * 32 + mf * 16 + g4;
        int rh = rl + 8;
        float s0 = 0.f, s1 = 0.f;
#pragma unroll
        for (int nf = 0; nf < 8; nf++) {
            int c = warpN * 64 + nf * 8 + q2;
            float b0 = sb[c], b1 = sb[c + 1];
            float w0 = sa[c], w1 = sa[c + 1];
            float h0 = acc[mf][nf][0] + b0, h1 = acc[mf][nf][1] + b1;
            float h2 = acc[mf][nf][2] + b0, h3 = acc[mf][nf][3] + b1;
            if (r0 + rl < N) hh[(long)(r0 + rl) * 64 + (c >> 1)] = __floats2half2_rn(h0, h1);
            if (r0 + rh < N) hh[(long)(r0 + rh) * 64 + (c >> 1)] = __floats2half2_rn(h2, h3);
            s0 += fabsf(h0) * w0 + fabsf(h1) * w1;
            s1 += fabsf(h2) * w0 + fabsf(h3) * w1;
        }
        atomicAdd(&a2s[rl], s0);
        atomicAdd(&a2s[rh], s1);
    }
    __syncthreads();
    if (t < 128 && r0 + t < N) g_e[r0 + t] = __expf(a2s[t]);
}

// ---------------------------------------------------------------------------
__global__ void k_hist(const int* __restrict__ row, int E) {
    int e = blockIdx.x * blockDim.x + threadIdx.x;
    if (e < E) atomicAdd(&g_cnt[row[e]], 1);
}

__global__ __launch_bounds__(1024) void k_scan1(int N) {
    int i    = blockIdx.x * 1024 + threadIdx.x;
    int lane = threadIdx.x & 31;
    int wid  = threadIdx.x >> 5;
    int v = (i < N) ? g_cnt[i] : 0;
    int x = v;
#pragma unroll
    for (int o = 1; o < 32; o <<= 1) {
        int y = __shfl_up_sync(0xffffffffu, x, o);
        if (lane >= o) x += y;
    }
    __shared__ int wsum[32];
    if (lane == 31) wsum[wid] = x;
    __syncthreads();
    if (wid == 0) {
        int w = wsum[lane];
#pragma unroll
        for (int o = 1; o < 32; o <<= 1) {
            int y = __shfl_up_sync(0xffffffffu, w, o);
            if (lane >= o) w += y;
        }
        wsum[lane] = w;
    }
    __syncthreads();
    int incl = x + (wid > 0 ? wsum[wid - 1] : 0);
    if (i < N) g_off[i] = incl - v;
    if (threadIdx.x == 1023) g_bsum[blockIdx.x] = incl;
}

__global__ __launch_bounds__(128) void k_scan2(int nb) {
    __shared__ int s[128];
    int t = threadIdx.x;
    int v = (t < nb) ? g_bsum[t] : 0;
    s[t] = v;
    __syncthreads();
#pragma unroll
    for (int o = 1; o < 128; o <<= 1) {
        int y = (t >= o) ? s[t - o] : 0;
        __syncthreads();
        s[t] += y;
        __syncthreads();
    }
    if (t < nb) g_bsum[t] = s[t] - v;
}

__global__ void k_scan3(int N, int E) {
    int i = blockIdx.x * blockDim.x + threadIdx.x;
    if (i < N) {
        int val = g_off[i] + g_bsum[i >> 10];
        g_off[i] = val;
        g_cur[i] = val;
    }
    if (i == 0) g_off[N] = E;
}

__global__ void k_scatter(const int* __restrict__ row, const int* __restrict__ col,
                          const float* __restrict__ values, int E) {
    int e = blockIdx.x * blockDim.x + threadIdx.x;
    if (e < E) {
        int p = atomicAdd(&g_cur[row[e]], 1);
        g_col[p] = (unsigned)col[e] | (values[e] < 0.f ? 0x80000000u : 0u);
    }
}

// ---------------------------------------------------------------------------
// One warp per row, SINGLE pass: d += e[col]; acc += sign*e[col]*h[col].
// No max shift (logits span < +-2), no per-row reductions (d identical in
// all lanes since col/e loads are broadcast). out = acc / d.
__global__ __launch_bounds__(256) void k_spmm(float4* __restrict__ out4, int N) {
    int gw   = (blockIdx.x * blockDim.x + threadIdx.x) >> 5;
    int lane = threadIdx.x & 31;
    if (gw >= N) return;

    int base = g_off[gw];
    int end  = g_off[gw + 1];

    if (end == base) {
        out4[gw * 32 + lane] = make_float4(0.f, 0.f, 0.f, 0.f);
        return;
    }

    const uint2* hh2 = (const uint2*)g_hh;
    float d = 0.f;
    float4 acc = make_float4(0.f, 0.f, 0.f, 0.f);
#pragma unroll 2
    for (int j = base; j < end; ++j) {
        unsigned ce = g_col[j];                    // broadcast
        int c = (int)(ce & 0x7fffffffu);
        float e = g_e[c];                          // broadcast
        float w = (ce & 0x80000000u) ? -e : e;
        uint2 hv = hh2[c * 32 + lane];             // 256B/warp gather (L2)
        float2 f01 = __half22float2(*(const __half2*)&hv.x);
        float2 f23 = __half22float2(*(const __half2*)&hv.y);
        d += e;
        acc.x += w * f01.x;
        acc.y += w * f01.y;
        acc.z += w * f23.x;
        acc.w += w * f23.y;
    }
    float inv = 1.f / d;
    acc.x *= inv; acc.y *= inv; acc.z *= inv; acc.w *= inv;
    out4[gw * 32 + lane] = acc;
}

// ---------------------------------------------------------------------------
extern "C" void kernel_launch(void* const* d_in, const int* in_sizes, int n_in,
                              void* d_out, int out_size) {
    const float* feat   = (const float*)d_in[0];
    const float* values = (const float*)d_in[1];
    const float* W      = (const float*)d_in[2];
    const float* bias   = (const float*)d_in[3];
    const float* a2w    = (const float*)d_in[6];   // a1 terms cancel in row-softmax
    const int*   row    = (const int*)d_in[8];
    const int*   col    = (const int*)d_in[9];

    const int N = in_sizes[0] / DIN;
    const int E = in_sizes[1];

    cudaFuncSetAttribute(k_gemm, cudaFuncAttributeMaxDynamicSharedMemorySize,
                         SMEM_DYN);

    int nb = (N + 1023) / 1024;

    k_zero<<<(N + 255) / 256, 256>>>(N);
    k_wconv<<<(DIN * DOUT + 255) / 256, 256>>>(W);
    k_hist<<<(E + 255) / 256, 256>>>(row, E);
    k_scan1<<<nb, 1024>>>(N);
    k_scan2<<<1, 128>>>(nb);
    k_gemm<<<(N + 127) / 128, 256, SMEM_DYN>>>(feat, bias, a2w, N);
    k_scan3<<<(N + 255) / 256, 256>>>(N, E);
    k_scatter<<<(E + 255) / 256, 256>>>(row, col, values, E);

    long long warps = (long long)N;
    int blocks = (int)((warps * 32 + 255) / 256);
    k_spmm<<<blocks, 256>>>((float4*)d_out, N);
}

// round 7
// speedup vs baseline: 2.1653x; 1.0983x over previous
#include <cuda_runtime.h>
#include <cuda_fp16.h>
#include <math.h>

#define NMAX 100000
#define EMAX 1600000
#define DIN  256
#define DOUT 128

// ---- scratch (device globals; no allocations allowed) ----
__device__ uint4 g_hh[NMAX * 16];      // h in fp16: 128 halves/row (25.6MB, L2-resident)
__device__ float g_e[NMAX];            // e[n] = exp(sum_c |h|*a2_w)
__device__ int   g_cnt[NMAX];
__device__ int   g_off[NMAX + 1];
__device__ int   g_cur[NMAX];
__device__ unsigned g_col[EMAX];       // CSR col, bit31 = sign(value)
__device__ int   g_bsum[128];
__device__ __half g_wt[DOUT * DIN];    // W^T [n][k] fp16

// ---------------------------------------------------------------------------
// fused: zero histogram + convert W [k][n] fp32 -> W^T fp16 [n][k]
__global__ void k_init(const float* __restrict__ W, int N) {
    int i = blockIdx.x * blockDim.x + threadIdx.x;
    if (i < N) g_cnt[i] = 0;
    if (i < DIN * DOUT) {
        int k = i >> 7, n = i & 127;
        g_wt[n * DIN + k] = __float2half_rn(W[i]);
    }
}

// ---------------------------------------------------------------------------
// HMMA fp16 GEMM, double-buffered, ldmatrix fragments.
// CTA: 256 thr, tile M=128 x N=128; warp tile 32x64. K chunked by 64.
// Fused epilogue: +bias, fp16 h store, e = exp(sum |h|*a2_w).

#define PAD 72
#define OFF_CONST 0                     // bias[128] + a2w[128]
#define STAGE_BYTES (128 * PAD * 2)
#define OFF_A0    1024
#define OFF_B0    (OFF_A0 + STAGE_BYTES)
#define OFF_A1    (OFF_B0 + STAGE_BYTES)
#define OFF_B1    (OFF_A1 + STAGE_BYTES)
#define SMEM_DYN  (OFF_B1 + STAGE_BYTES)

__device__ __forceinline__ void mma16816(float* d, const unsigned* a,
                                         const unsigned* b) {
    asm volatile(
        "mma.sync.aligned.m16n8k16.row.col.f32.f16.f16.f32 "
        "{%0,%1,%2,%3}, {%4,%5,%6,%7}, {%8,%9}, {%0,%1,%2,%3};"
        : "+f"(d[0]), "+f"(d[1]), "+f"(d[2]), "+f"(d[3])
        : "r"(a[0]), "r"(a[1]), "r"(a[2]), "r"(a[3]), "r"(b[0]), "r"(b[1]));
}
__device__ __forceinline__ void ldmx4(unsigned* r, unsigned addr) {
    asm volatile(
        "ldmatrix.sync.aligned.m8n8.x4.shared.b16 {%0,%1,%2,%3}, [%4];"
        : "=r"(r[0]), "=r"(r[1]), "=r"(r[2]), "=r"(r[3]) : "r"(addr));
}

__global__ __launch_bounds__(256, 2) void k_gemm(const float* __restrict__ feat,
                                                 const float* __restrict__ bias,
                                                 const float* __restrict__ a2w,
                                                 int N) {
    extern __shared__ char smem[];
    float* sb = (float*)(smem + OFF_CONST);
    float* sa = sb + 128;

    const int t     = threadIdx.x;
    const int lane  = t & 31;
    const int wid   = t >> 5;
    const int warpM = wid & 3;
    const int warpN = wid >> 2;
    const int r0    = blockIdx.x * 128;
    const int q2    = (lane & 3) << 1;
    const int g4    = lane >> 2;

    if (t < 128) { sb[t] = bias[t]; sa[t] = a2w[t]; }

    float acc[2][8][4];
#pragma unroll
    for (int mf = 0; mf < 2; mf++)
#pragma unroll
        for (int nf = 0; nf < 8; nf++)
#pragma unroll
            for (int j = 0; j < 4; j++) acc[mf][nf][j] = 0.f;

    const float4* feat4 = (const float4*)feat;
    const uint4*  wt4   = (const uint4*)g_wt;

    // per-thread staging geometry (4 segs of 8 elements each, per chunk)
    int arow[4], ak8[4];
#pragma unroll
    for (int i = 0; i < 4; i++) {
        int seg = t + i * 256;
        arow[i] = seg >> 3;
        ak8[i]  = seg & 7;
    }

    // ldmatrix per-lane addresses (stage 0)
    const unsigned sb32 = (unsigned)__cvta_generic_to_shared(smem);
    const int tl   = lane >> 3;          // tile index 0..3
    const int lrow = lane & 7;
    unsigned aAddr[2], bAddr[4];
#pragma unroll
    for (int mf = 0; mf < 2; mf++) {
        int row = warpM * 32 + mf * 16 + (tl & 1) * 8 + lrow;
        int col = (tl >> 1) * 8;
        aAddr[mf] = sb32 + OFF_A0 + (unsigned)(row * PAD + col) * 2u;
    }
#pragma unroll
    for (int nfp = 0; nfp < 4; nfp++) {
        int row = warpN * 64 + nfp * 16 + ((tl >> 1) & 1) * 8 + lrow;
        int col = (tl & 1) * 8;
        bAddr[nfp] = sb32 + OFF_B0 + (unsigned)(row * PAD + col) * 2u;
    }

    uint4 aReg[4], bReg[4];
    auto ldchunk = [&](int kc) {
#pragma unroll
        for (int i = 0; i < 4; i++) {
            int gr = r0 + arow[i];
            float4 f0 = make_float4(0.f, 0.f, 0.f, 0.f), f1 = f0;
            if (gr < N) {
                f0 = feat4[gr * 64 + kc * 16 + ak8[i] * 2 + 0];
                f1 = feat4[gr * 64 + kc * 16 + ak8[i] * 2 + 1];
            }
            __half hb[8];
            hb[0] = __float2half_rn(f0.x); hb[1] = __float2half_rn(f0.y);
            hb[2] = __float2half_rn(f0.z); hb[3] = __float2half_rn(f0.w);
            hb[4] = __float2half_rn(f1.x); hb[5] = __float2half_rn(f1.y);
            hb[6] = __float2half_rn(f1.z); hb[7] = __float2half_rn(f1.w);
            aReg[i] = *(const uint4*)hb;
            bReg[i] = wt4[arow[i] * 32 + kc * 8 + ak8[i]];
        }
    };
    auto stchunk = [&](int stg) {
        __half* A = (__half*)(smem + (stg ? OFF_A1 : OFF_A0));
        __half* B = (__half*)(smem + (stg ? OFF_B1 : OFF_B0));
#pragma unroll
        for (int i = 0; i < 4; i++) {
            *(uint4*)&A[arow[i] * PAD + ak8[i] * 8] = aReg[i];
            *(uint4*)&B[arow[i] * PAD + ak8[i] * 8] = bReg[i];
        }
    };

    ldchunk(0);
    stchunk(0);
    __syncthreads();

    for (int kc = 0; kc < 4; kc++) {
        if (kc < 3) ldchunk(kc + 1);            // overlap with MMA below

        const unsigned stg = (kc & 1) ? (unsigned)(2 * STAGE_BYTES) : 0u;
#pragma unroll
        for (int ks = 0; ks < 4; ks++) {
            const unsigned ko = stg + (unsigned)(ks * 32);
            unsigned a0[4], a1[4];
            ldmx4(a0, aAddr[0] + ko);
            ldmx4(a1, aAddr[1] + ko);
#pragma unroll
            for (int nfp = 0; nfp < 4; nfp++) {
                unsigned b4[4];
                ldmx4(b4, bAddr[nfp] + ko);
                mma16816(acc[0][2 * nfp + 0], a0, b4 + 0);
                mma16816(acc[1][2 * nfp + 0], a1, b4 + 0);
                mma16816(acc[0][2 * nfp + 1], a0, b4 + 2);
                mma16816(acc[1][2 * nfp + 1], a1, b4 + 2);
            }
        }
        __syncthreads();
        if (kc < 3) {
            stchunk((kc + 1) & 1);
            __syncthreads();
        }
    }

    // --- epilogue ---
    float* a2s = (float*)(smem + OFF_A0);   // reuse tile smem (post-sync)
    if (t < 128) a2s[t] = 0.f;
    __syncthreads();

    __half2* hh = (__half2*)g_hh;
#pragma unroll
    for (int mf = 0; mf < 2; mf++) {
        int rl = warpM * 32 + mf * 16 + g4;
        int rh = rl + 8;
        float s0 = 0.f, s1 = 0.f;
#pragma unroll
        for (int nf = 0; nf < 8; nf++) {
            int c = warpN * 64 + nf * 8 + q2;
            float b0 = sb[c], b1 = sb[c + 1];
            float w0 = sa[c], w1 = sa[c + 1];
            float h0 = acc[mf][nf][0] + b0, h1 = acc[mf][nf][1] + b1;
            float h2 = acc[mf][nf][2] + b0, h3 = acc[mf][nf][3] + b1;
            if (r0 + rl < N) hh[(long)(r0 + rl) * 64 + (c >> 1)] = __floats2half2_rn(h0, h1);
            if (r0 + rh < N) hh[(long)(r0 + rh) * 64 + (c >> 1)] = __floats2half2_rn(h2, h3);
            s0 += fabsf(h0) * w0 + fabsf(h1) * w1;
            s1 += fabsf(h2) * w0 + fabsf(h3) * w1;
        }
        atomicAdd(&a2s[rl], s0);
        atomicAdd(&a2s[rh], s1);
    }
    __syncthreads();
    if (t < 128 && r0 + t < N) g_e[r0 + t] = __expf(a2s[t]);
}

// ---------------------------------------------------------------------------
__global__ void k_hist(const int* __restrict__ row, int E) {
    int e = blockIdx.x * blockDim.x + threadIdx.x;
    if (e < E) atomicAdd(&g_cnt[row[e]], 1);
}

__global__ __launch_bounds__(1024) void k_scan1(int N) {
    int i    = blockIdx.x * 1024 + threadIdx.x;
    int lane = threadIdx.x & 31;
    int wid  = threadIdx.x >> 5;
    int v = (i < N) ? g_cnt[i] : 0;
    int x = v;
#pragma unroll
    for (int o = 1; o < 32; o <<= 1) {
        int y = __shfl_up_sync(0xffffffffu, x, o);
        if (lane >= o) x += y;
    }
    __shared__ int wsum[32];
    if (lane == 31) wsum[wid] = x;
    __syncthreads();
    if (wid == 0) {
        int w = wsum[lane];
#pragma unroll
        for (int o = 1; o < 32; o <<= 1) {
            int y = __shfl_up_sync(0xffffffffu, w, o);
            if (lane >= o) w += y;
        }
        wsum[lane] = w;
    }
    __syncthreads();
    int incl = x + (wid > 0 ? wsum[wid - 1] : 0);
    if (i < N) g_off[i] = incl - v;
    if (threadIdx.x == 1023) g_bsum[blockIdx.x] = incl;
}

__global__ __launch_bounds__(128) void k_scan2(int nb) {
    __shared__ int s[128];
    int t = threadIdx.x;
    int v = (t < nb) ? g_bsum[t] : 0;
    s[t] = v;
    __syncthreads();
#pragma unroll
    for (int o = 1; o < 128; o <<= 1) {
        int y = (t >= o) ? s[t - o] : 0;
        __syncthreads();
        s[t] += y;
        __syncthreads();
    }
    if (t < nb) g_bsum[t] = s[t] - v;
}

__global__ void k_scan3(int N, int E) {
    int i = blockIdx.x * blockDim.x + threadIdx.x;
    if (i < N) {
        int val = g_off[i] + g_bsum[i >> 10];
        g_off[i] = val;
        g_cur[i] = val;
    }
    if (i == 0) g_off[N] = E;
}

__global__ void k_scatter(const int* __restrict__ row, const int* __restrict__ col,
                          const float* __restrict__ values, int E) {
    int e = blockIdx.x * blockDim.x + threadIdx.x;
    if (e < E) {
        int p = atomicAdd(&g_cur[row[e]], 1);
        g_col[p] = (unsigned)col[e] | (values[e] < 0.f ? 0x80000000u : 0u);
    }
}

// ---------------------------------------------------------------------------
// TWO rows per warp (16 lanes each), single pass:
// d += e[col]; acc += sign*e[col]*h[col]; out = acc/d. No reductions needed.
__global__ __launch_bounds__(256) void k_spmm(float4* __restrict__ out4, int N) {
    int gw   = (blockIdx.x * blockDim.x + threadIdx.x) >> 5;
    int lane = threadIdx.x & 31;
    int r    = gw * 2 + (lane >> 4);       // row handled by this half-warp
    int lr   = lane & 15;
    if (r >= N) return;

    int base = g_off[r];
    int end  = g_off[r + 1];

    if (end == base) {
        out4[r * 32 + lr * 2 + 0] = make_float4(0.f, 0.f, 0.f, 0.f);
        out4[r * 32 + lr * 2 + 1] = make_float4(0.f, 0.f, 0.f, 0.f);
        return;
    }

    float d = 0.f;
    float a0 = 0.f, a1 = 0.f, a2 = 0.f, a3 = 0.f;
    float a4 = 0.f, a5 = 0.f, a6 = 0.f, a7 = 0.f;
#pragma unroll 2
    for (int j = base; j < end; ++j) {
        unsigned ce = g_col[j];                    // broadcast within half-warp
        int c = (int)(ce & 0x7fffffffu);
        float e = g_e[c];                          // broadcast
        float w = (ce & 0x80000000u) ? -e : e;
        uint4 hv = g_hh[c * 16 + lr];              // 256B per half-warp (L2)
        float2 f0 = __half22float2(*(const __half2*)&hv.x);
        float2 f1 = __half22float2(*(const __half2*)&hv.y);
        float2 f2 = __half22float2(*(const __half2*)&hv.z);
        float2 f3 = __half22float2(*(const __half2*)&hv.w);
        d += e;
        a0 += w * f0.x; a1 += w * f0.y;
        a2 += w * f1.x; a3 += w * f1.y;
        a4 += w * f2.x; a5 += w * f2.y;
        a6 += w * f3.x; a7 += w * f3.y;
    }
    float inv = 1.f / d;
    out4[r * 32 + lr * 2 + 0] = make_float4(a0 * inv, a1 * inv, a2 * inv, a3 * inv);
    out4[r * 32 + lr * 2 + 1] = make_float4(a4 * inv, a5 * inv, a6 * inv, a7 * inv);
}

// ---------------------------------------------------------------------------
extern "C" void kernel_launch(void* const* d_in, const int* in_sizes, int n_in,
                              void* d_out, int out_size) {
    const float* feat   = (const float*)d_in[0];
    const float* values = (const float*)d_in[1];
    const float* W      = (const float*)d_in[2];
    const float* bias   = (const float*)d_in[3];
    const float* a2w    = (const float*)d_in[6];   // a1 terms cancel in row-softmax
    const int*   row    = (const int*)d_in[8];
    const int*   col    = (const int*)d_in[9];

    const int N = in_sizes[0] / DIN;
    const int E = in_sizes[1];

    cudaFuncSetAttribute(k_gemm, cudaFuncAttributeMaxDynamicSharedMemorySize,
                         SMEM_DYN);

    int nb = (N + 1023) / 1024;

    k_init<<<(N + 255) / 256, 256>>>(W, N);
    k_hist<<<(E + 255) / 256, 256>>>(row, E);
    k_scan1<<<nb, 1024>>>(N);
    k_scan2<<<1, 128>>>(nb);
    k_gemm<<<(N + 127) / 128, 256, SMEM_DYN>>>(feat, bias, a2w, N);
    k_scan3<<<(N + 255) / 256, 256>>>(N, E);
    k_scatter<<<(E + 255) / 256, 256>>>(row, col, values, E);

    long long hw = ((long long)N + 1) / 2;         // 2 rows per warp
    int blocks = (int)((hw * 32 + 255) / 256);
    k_spmm<<<blocks, 256>>>((float4*)d_out, N);
}

// round 8
// speedup vs baseline: 2.4169x; 1.1162x over previous
#include <cuda_runtime.h>
#include <cuda_fp16.h>
#include <math.h>

#define NMAX 100000
#define EMAX 1600000
#define DIN  256
#define DOUT 128

// ---- scratch (device globals; no allocations allowed) ----
__device__ uint4 g_hh[NMAX * 16];      // h in fp16: 128 halves/row (25.6MB, L2-resident)
__device__ float g_e[NMAX];            // e[n] = exp(sum_c |h|*a2_w)
__device__ int   g_cnt[NMAX];
__device__ int   g_off[NMAX + 1];
__device__ int   g_cur[NMAX];
__device__ unsigned g_col[EMAX];       // CSR col, bit31 = sign(value)
__device__ int   g_bsum[128];
__device__ __half g_wt[DOUT * DIN];    // W^T [n][k] fp16

// ---------------------------------------------------------------------------
// fused: zero histogram + convert W [k][n] fp32 -> W^T fp16 [n][k]
__global__ void k_init(const float* __restrict__ W, int N) {
    int i = blockIdx.x * blockDim.x + threadIdx.x;
    if (i < N) g_cnt[i] = 0;
    if (i < DIN * DOUT) {
        int k = i >> 7, n = i & 127;
        g_wt[n * DIN + k] = __float2half_rn(W[i]);
    }
}

// ---------------------------------------------------------------------------
// HMMA fp16 GEMM, double-buffered, ldmatrix fragments.
// CTA: 256 thr, tile M=128 x N=128; warp tile 32x64. K chunked by 64.
// Fused epilogue: +bias, fp16 h store, e = exp(sum |h|*a2_w).

#define PAD 72
#define OFF_CONST 0                     // bias[128] + a2w[128]
#define STAGE_BYTES (128 * PAD * 2)
#define OFF_A0    1024
#define OFF_B0    (OFF_A0 + STAGE_BYTES)
#define OFF_A1    (OFF_B0 + STAGE_BYTES)
#define OFF_B1    (OFF_A1 + STAGE_BYTES)
#define SMEM_DYN  (OFF_B1 + STAGE_BYTES)

__device__ __forceinline__ void mma16816(float* d, const unsigned* a,
                                         const unsigned* b) {
    asm volatile(
        "mma.sync.aligned.m16n8k16.row.col.f32.f16.f16.f32 "
        "{%0,%1,%2,%3}, {%4,%5,%6,%7}, {%8,%9}, {%0,%1,%2,%3};"
        : "+f"(d[0]), "+f"(d[1]), "+f"(d[2]), "+f"(d[3])
        : "r"(a[0]), "r"(a[1]), "r"(a[2]), "r"(a[3]), "r"(b[0]), "r"(b[1]));
}
__device__ __forceinline__ void ldmx4(unsigned* r, unsigned addr) {
    asm volatile(
        "ldmatrix.sync.aligned.m8n8.x4.shared.b16 {%0,%1,%2,%3}, [%4];"
        : "=r"(r[0]), "=r"(r[1]), "=r"(r[2]), "=r"(r[3]) : "r"(addr));
}

__global__ __launch_bounds__(256, 2) void k_gemm(const float* __restrict__ feat,
                                                 const float* __restrict__ bias,
                                                 const float* __restrict__ a2w,
                                                 int N) {
    extern __shared__ char smem[];
    float* sb = (float*)(smem + OFF_CONST);
    float* sa = sb + 128;

    const int t     = threadIdx.x;
    const int lane  = t & 31;
    const int wid   = t >> 5;
    const int warpM = wid & 3;
    const int warpN = wid >> 2;
    const int r0    = blockIdx.x * 128;
    const int q2    = (lane & 3) << 1;
    const int g4    = lane >> 2;

    if (t < 128) { sb[t] = bias[t]; sa[t] = a2w[t]; }

    float acc[2][8][4];
#pragma unroll
    for (int mf = 0; mf < 2; mf++)
#pragma unroll
        for (int nf = 0; nf < 8; nf++)
#pragma unroll
            for (int j = 0; j < 4; j++) acc[mf][nf][j] = 0.f;

    const float4* feat4 = (const float4*)feat;
    const uint4*  wt4   = (const uint4*)g_wt;

    // per-thread staging geometry (4 segs of 8 elements each, per chunk)
    int arow[4], ak8[4];
#pragma unroll
    for (int i = 0; i < 4; i++) {
        int seg = t + i * 256;
        arow[i] = seg >> 3;
        ak8[i]  = seg & 7;
    }

    // ldmatrix per-lane addresses (stage 0)
    const unsigned sb32 = (unsigned)__cvta_generic_to_shared(smem);
    const int tl   = lane >> 3;          // tile index 0..3
    const int lrow = lane & 7;
    unsigned aAddr[2], bAddr[4];
#pragma unroll
    for (int mf = 0; mf < 2; mf++) {
        int row = warpM * 32 + mf * 16 + (tl & 1) * 8 + lrow;
        int col = (tl >> 1) * 8;
        aAddr[mf] = sb32 + OFF_A0 + (unsigned)(row * PAD + col) * 2u;
    }
#pragma unroll
    for (int nfp = 0; nfp < 4; nfp++) {
        int row = warpN * 64 + nfp * 16 + ((tl >> 1) & 1) * 8 + lrow;
        int col = (tl & 1) * 8;
        bAddr[nfp] = sb32 + OFF_B0 + (unsigned)(row * PAD + col) * 2u;
    }

    uint4 aReg[4], bReg[4];
    auto ldchunk = [&](int kc) {
#pragma unroll
        for (int i = 0; i < 4; i++) {
            int gr = r0 + arow[i];
            float4 f0 = make_float4(0.f, 0.f, 0.f, 0.f), f1 = f0;
            if (gr < N) {
                f0 = feat4[gr * 64 + kc * 16 + ak8[i] * 2 + 0];
                f1 = feat4[gr * 64 + kc * 16 + ak8[i] * 2 + 1];
            }
            __half hb[8];
            hb[0] = __float2half_rn(f0.x); hb[1] = __float2half_rn(f0.y);
            hb[2] = __float2half_rn(f0.z); hb[3] = __float2half_rn(f0.w);
            hb[4] = __float2half_rn(f1.x); hb[5] = __float2half_rn(f1.y);
            hb[6] = __float2half_rn(f1.z); hb[7] = __float2half_rn(f1.w);
            aReg[i] = *(const uint4*)hb;
            bReg[i] = wt4[arow[i] * 32 + kc * 8 + ak8[i]];
        }
    };
    auto stchunk = [&](int stg) {
        __half* A = (__half*)(smem + (stg ? OFF_A1 : OFF_A0));
        __half* B = (__half*)(smem + (stg ? OFF_B1 : OFF_B0));
#pragma unroll
        for (int i = 0; i < 4; i++) {
            *(uint4*)&A[arow[i] * PAD + ak8[i] * 8] = aReg[i];
            *(uint4*)&B[arow[i] * PAD + ak8[i] * 8] = bReg[i];
        }
    };

    ldchunk(0);
    stchunk(0);
    __syncthreads();

    for (int kc = 0; kc < 4; kc++) {
        if (kc < 3) ldchunk(kc + 1);            // overlap with MMA below

        const unsigned stg = (kc & 1) ? (unsigned)(2 * STAGE_BYTES) : 0u;
#pragma unroll
        for (int ks = 0; ks < 4; ks++) {
            const unsigned ko = stg + (unsigned)(ks * 32);
            unsigned a0[4], a1[4];
            ldmx4(a0, aAddr[0] + ko);
            ldmx4(a1, aAddr[1] + ko);
#pragma unroll
            for (int nfp = 0; nfp < 4; nfp++) {
                unsigned b4[4];
                ldmx4(b4, bAddr[nfp] + ko);
                mma16816(acc[0][2 * nfp + 0], a0, b4 + 0);
                mma16816(acc[1][2 * nfp + 0], a1, b4 + 0);
                mma16816(acc[0][2 * nfp + 1], a0, b4 + 2);
                mma16816(acc[1][2 * nfp + 1], a1, b4 + 2);
            }
        }
        __syncthreads();
        if (kc < 3) {
            stchunk((kc + 1) & 1);
            __syncthreads();
        }
    }

    // --- epilogue ---
    float* a2s = (float*)(smem + OFF_A0);   // reuse tile smem (post-sync)
    if (t < 128) a2s[t] = 0.f;
    __syncthreads();

    __half2* hh = (__half2*)g_hh;
#pragma unroll
    for (int mf = 0; mf < 2; mf++) {
        int rl = warpM * 32 + mf * 16 + g4;
        int rh = rl + 8;
        float s0 = 0.f, s1 = 0.f;
#pragma unroll
        for (int nf = 0; nf < 8; nf++) {
            int c = warpN * 64 + nf * 8 + q2;
            float b0 = sb[c], b1 = sb[c + 1];
            float w0 = sa[c], w1 = sa[c + 1];
            float h0 = acc[mf][nf][0] + b0, h1 = acc[mf][nf][1] + b1;
            float h2 = acc[mf][nf][2] + b0, h3 = acc[mf][nf][3] + b1;
            if (r0 + rl < N) hh[(long)(r0 + rl) * 64 + (c >> 1)] = __floats2half2_rn(h0, h1);
            if (r0 + rh < N) hh[(long)(r0 + rh) * 64 + (c >> 1)] = __floats2half2_rn(h2, h3);
            s0 += fabsf(h0) * w0 + fabsf(h1) * w1;
            s1 += fabsf(h2) * w0 + fabsf(h3) * w1;
        }
        atomicAdd(&a2s[rl], s0);
        atomicAdd(&a2s[rh], s1);
    }
    __syncthreads();
    if (t < 128 && r0 + t < N) g_e[r0 + t] = __expf(a2s[t]);
}

// ---------------------------------------------------------------------------
__global__ void k_hist(const int* __restrict__ row, int E) {
    int e = blockIdx.x * blockDim.x + threadIdx.x;
    if (e < E) atomicAdd(&g_cnt[row[e]], 1);
}

__global__ __launch_bounds__(1024) void k_scan1(int N) {
    int i    = blockIdx.x * 1024 + threadIdx.x;
    int lane = threadIdx.x & 31;
    int wid  = threadIdx.x >> 5;
    int v = (i < N) ? g_cnt[i] : 0;
    int x = v;
#pragma unroll
    for (int o = 1; o < 32; o <<= 1) {
        int y = __shfl_up_sync(0xffffffffu, x, o);
        if (lane >= o) x += y;
    }
    __shared__ int wsum[32];
    if (lane == 31) wsum[wid] = x;
    __syncthreads();
    if (wid == 0) {
        int w = wsum[lane];
#pragma unroll
        for (int o = 1; o < 32; o <<= 1) {
            int y = __shfl_up_sync(0xffffffffu, w, o);
            if (lane >= o) w += y;
        }
        wsum[lane] = w;
    }
    __syncthreads();
    int incl = x + (wid > 0 ? wsum[wid - 1] : 0);
    if (i < N) g_off[i] = incl - v;
    if (threadIdx.x == 1023) g_bsum[blockIdx.x] = incl;
}

__global__ __launch_bounds__(128) void k_scan2(int nb) {
    __shared__ int s[128];
    int t = threadIdx.x;
    int v = (t < nb) ? g_bsum[t] : 0;
    s[t] = v;
    __syncthreads();
#pragma unroll
    for (int o = 1; o < 128; o <<= 1) {
        int y = (t >= o) ? s[t - o] : 0;
        __syncthreads();
        s[t] += y;
        __syncthreads();
    }
    if (t < nb) g_bsum[t] = s[t] - v;
}

__global__ void k_scan3(int N, int E) {
    int i = blockIdx.x * blockDim.x + threadIdx.x;
    if (i < N) {
        int val = g_off[i] + g_bsum[i >> 10];
        g_off[i] = val;
        g_cur[i] = val;
    }
    if (i == 0) g_off[N] = E;
}

__global__ void k_scatter(const int* __restrict__ row, const int* __restrict__ col,
                          const float* __restrict__ values, int E) {
    int e = blockIdx.x * blockDim.x + threadIdx.x;
    if (e < E) {
        int p = atomicAdd(&g_cur[row[e]], 1);
        g_col[p] = (unsigned)col[e] | (values[e] < 0.f ? 0x80000000u : 0u);
    }
}

// ---------------------------------------------------------------------------
// TWO rows per warp (16 lanes each), single pass:
// d += e[col]; acc += sign*e[col]*h[col]; out = acc/d. No reductions needed.
__global__ __launch_bounds__(256) void k_spmm(float4* __restrict__ out4, int N) {
    int gw   = (blockIdx.x * blockDim.x + threadIdx.x) >> 5;
    int lane = threadIdx.x & 31;
    int r    = gw * 2 + (lane >> 4);       // row handled by this half-warp
    int lr   = lane & 15;
    if (r >= N) return;

    int base = g_off[r];
    int end  = g_off[r + 1];

    if (end == base) {
        out4[r * 32 + lr * 2 + 0] = make_float4(0.f, 0.f, 0.f, 0.f);
        out4[r * 32 + lr * 2 + 1] = make_float4(0.f, 0.f, 0.f, 0.f);
        return;
    }

    float d = 0.f;
    float a0 = 0.f, a1 = 0.f, a2 = 0.f, a3 = 0.f;
    float a4 = 0.f, a5 = 0.f, a6 = 0.f, a7 = 0.f;
#pragma unroll 2
    for (int j = base; j < end; ++j) {
        unsigned ce = g_col[j];                    // broadcast within half-warp
        int c = (int)(ce & 0x7fffffffu);
        float e = g_e[c];                          // broadcast
        float w = (ce & 0x80000000u) ? -e : e;
        uint4 hv = g_hh[c * 16 + lr];              // 256B per half-warp (L2)
        float2 f0 = __half22float2(*(const __half2*)&hv.x);
        float2 f1 = __half22float2(*(const __half2*)&hv.y);
        float2 f2 = __half22float2(*(const __half2*)&hv.z);
        float2 f3 = __half22float2(*(const __half2*)&hv.w);
        d += e;
        a0 += w * f0.x; a1 += w * f0.y;
        a2 += w * f1.x; a3 += w * f1.y;
        a4 += w * f2.x; a5 += w * f2.y;
        a6 += w * f3.x; a7 += w * f3.y;
    }
    float inv = 1.f / d;
    out4[r * 32 + lr * 2 + 0] = make_float4(a0 * inv, a1 * inv, a2 * inv, a3 * inv);
    out4[r * 32 + lr * 2 + 1] = make_float4(a4 * inv, a5 * inv, a6 * inv, a7 * inv);
}

// ---------------------------------------------------------------------------
extern "C" void kernel_launch(void* const* d_in, const int* in_sizes, int n_in,
                              void* d_out, int out_size) {
    const float* feat   = (const float*)d_in[0];
    const float* values = (const float*)d_in[1];
    const float* W      = (const float*)d_in[2];
    const float* bias   = (const float*)d_in[3];
    const float* a2w    = (const float*)d_in[6];   // a1 terms cancel in row-softmax
    const int*   row    = (const int*)d_in[8];
    const int*   col    = (const int*)d_in[9];

    const int N = in_sizes[0] / DIN;
    const int E = in_sizes[1];

    // one-time host resources (no device memory; identical work every call)
    static cudaStream_t s2 = nullptr;
    static cudaEvent_t evFork = nullptr, evJoin = nullptr;
    if (!s2) {
        cudaStreamCreateWithFlags(&s2, cudaStreamNonBlocking);
        cudaEventCreateWithFlags(&evFork, cudaEventDisableTiming);
        cudaEventCreateWithFlags(&evJoin, cudaEventDisableTiming);
        cudaFuncSetAttribute(k_gemm, cudaFuncAttributeMaxDynamicSharedMemorySize,
                             SMEM_DYN);
    }

    int nb = (N + 1023) / 1024;

    // common root: zero hist + convert W
    k_init<<<(N + 255) / 256, 256>>>(W, N);

    // fork: CSR chain on s2, GEMM on main stream (independent until spmm)
    cudaEventRecord(evFork, 0);
    cudaStreamWaitEvent(s2, evFork, 0);

    k_hist<<<(E + 255) / 256, 256, 0, s2>>>(row, E);
    k_scan1<<<nb, 1024, 0, s2>>>(N);
    k_scan2<<<1, 128, 0, s2>>>(nb);
    k_scan3<<<(N + 255) / 256, 256, 0, s2>>>(N, E);
    k_scatter<<<(E + 255) / 256, 256, 0, s2>>>(row, col, values, E);
    cudaEventRecord(evJoin, s2);

    k_gemm<<<(N + 127) / 128, 256, SMEM_DYN>>>(feat, bias, a2w, N);

    // join: spmm needs both chains
    cudaStreamWaitEvent(0, evJoin, 0);
    long long hw = ((long long)N + 1) / 2;         // 2 rows per warp
    int blocks = (int)((hw * 32 + 255) / 256);
    k_spmm<<<blocks, 256>>>((float4*)d_out, N);
}